// round 15
// baseline (speedup 1.0000x reference)
#include <cuda_runtime.h>
#include <math.h>

#define B 32
#define D 512
#define H 1024
#define H3 (3*H)
#define NBLK 128
#define NTHR 512
#define NW   16            // warps per block
#define KPX 256            // x feature-pairs
#define KPH 512            // h feature-pairs
#define KPA (KPX+KPH)      // 768 combined feature-pairs (phase A)
#define SST 9              // padded smem slot stride (ull), 8 payload + 1 pad

// smem layout (ull units) — r12/r14 proven layout
#define SM_ARZ 0                       // 12288 ull  (6144 ulonglong2)
#define SM_AN  12288                   //  6144 ull  (3072 ulonglong2)
#define SM_WD  18432                   //  4096 ull  (2048 ulonglong2)
#define SM_RED 22528                   //  4608 ull  (512 slots * 9)
#define SM_TOT 27136                   // 217088 bytes

typedef unsigned long long ull;

// ---------------- persistent device scratch --------------------------------
__device__ __align__(16) float g_Wcomb[H3 * D];            // temp: W_ih @ W_enc
__device__ float g_bcomb[H3];
__device__ __align__(16) ulonglong2 g_WArz[NBLK * KPA * 8];
__device__ __align__(16) ulonglong2 g_WAn [NBLK * KPA * 4];
__device__ __align__(16) ulonglong2 g_WD  [NBLK * KPH * 4];
__device__ __align__(16) ull g_act[2][KPA * B + 64];
__device__ unsigned g_arrive;
__device__ unsigned g_base;     // snapshot of g_arrive at launch start

// ---------------- packed f32x2 helpers --------------------------------------
__device__ __forceinline__ void fma2(ull& acc, ull a, ull b) {
    asm("fma.rn.f32x2 %0, %1, %2, %0;" : "+l"(acc) : "l"(a), "l"(b));
}
__device__ __forceinline__ ull add2o(ull a, ull b) {
    ull c;
    asm("add.rn.f32x2 %0, %1, %2;" : "=l"(c) : "l"(a), "l"(b));
    return c;
}
__device__ __forceinline__ float2 upk(ull u) {
    float a, b;
    asm("mov.b64 {%0, %1}, %2;" : "=f"(a), "=f"(b) : "l"(u));
    return make_float2(a, b);
}
__device__ __forceinline__ ull packf2(float lo, float hi) {
    ull u; asm("mov.b64 %0, {%1, %2};" : "=l"(u) : "f"(lo), "f"(hi)); return u;
}

// ---------------- fast-math-immune precise fp32 transcendentals ------------
__device__ __forceinline__ float exp_acc(float x) {
    x = fminf(fmaxf(x, -80.f), 80.f);
    float t = fmaf(x, 1.4426950408889634f, 12582912.f);
    float k = t - 12582912.f;
    float r = fmaf(k, -0.693359375f, x);
    r = fmaf(k, 2.12194440054690583e-4f, r);
    float p = 1.9841269841e-4f;
    p = fmaf(p, r, 1.3888888889e-3f);
    p = fmaf(p, r, 8.3333333333e-3f);
    p = fmaf(p, r, 4.1666666667e-2f);
    p = fmaf(p, r, 1.6666666667e-1f);
    p = fmaf(p, r, 0.5f);
    float y = fmaf(p, r * r, r) + 1.0f;
    int ki = (int)k;
    float s = __int_as_float((ki + 127) << 23);
    return y * s;
}
__device__ __forceinline__ float sigmoid_acc(float x) {
    return __frcp_rn(1.0f + exp_acc(-x));
}
__device__ __forceinline__ float tanh_acc(float x) {
    float ax = fabsf(x);
    float e = exp_acc(2.0f * ax);
    float t = fmaf(-2.0f, __frcp_rn(e + 1.0f), 1.0f);
    return (x < 0.f) ? -t : t;
}

// ---------------- precompute: W_comb = W_ih @ W_enc (Kahan) -----------------
__global__ void __launch_bounds__(256) precompute_wcomb(
    const float* __restrict__ W_ih, const float* __restrict__ W_enc)
{
    __shared__ float wih[8][H];
    int r0 = blockIdx.x * 8;
    for (int i = threadIdx.x; i < 8 * H; i += 256)
        wih[i >> 10][i & (H - 1)] = W_ih[(size_t)r0 * H + i];
    __syncthreads();
    int d0 = threadIdx.x, d1 = threadIdx.x + 256;
    float s[16], c[16];
    #pragma unroll
    for (int j = 0; j < 16; j++) { s[j] = 0.f; c[j] = 0.f; }
    for (int k = 0; k < H; k++) {
        float e0 = __ldg(&W_enc[(size_t)k * D + d0]);
        float e1 = __ldg(&W_enc[(size_t)k * D + d1]);
        #pragma unroll
        for (int j = 0; j < 8; j++) {
            float w = wih[j][k];
            float tp = __fmul_rn(w, e0);
            float y  = __fsub_rn(tp, c[2*j]);
            float s2 = __fadd_rn(s[2*j], y);
            c[2*j]   = __fsub_rn(__fsub_rn(s2, s[2*j]), y);
            s[2*j]   = s2;
            tp = __fmul_rn(w, e1);
            y  = __fsub_rn(tp, c[2*j+1]);
            s2 = __fadd_rn(s[2*j+1], y);
            c[2*j+1] = __fsub_rn(__fsub_rn(s2, s[2*j+1]), y);
            s[2*j+1] = s2;
        }
    }
    #pragma unroll
    for (int j = 0; j < 8; j++) {
        g_Wcomb[(size_t)(r0 + j) * D + d0] = s[2*j];
        g_Wcomb[(size_t)(r0 + j) * D + d1] = s[2*j+1];
    }
}

// ---------------- fused pack: pack_A + pack_D + bcomb ----------------------
#define NPA ((H * KPA) / 256)
#define NPD ((D * KPH) / 256)
#define NPB ((H3 + 255) / 256)

__global__ void __launch_bounds__(256) fused_pack(
    const float* __restrict__ W_hh,
    const float* __restrict__ W_dec,
    const float* __restrict__ W_ih,
    const float* __restrict__ b_enc,
    const float* __restrict__ b_gru)
{
    int bid = blockIdx.x;
    if (bid < NPA) {
        int idx = bid * 256 + threadIdx.x;   // j*KPA + kp
        int j  = idx / KPA;
        int kp = idx - j * KPA;
        int blk = j >> 3, c = j & 7, cg = c >> 1, ci = c & 1;
        float v[3][2];
        #pragma unroll
        for (int g = 0; g < 3; g++)
            #pragma unroll
            for (int e = 0; e < 2; e++) {
                int f = 2 * kp + e;
                v[g][e] = (f < D)
                    ? g_Wcomb[(size_t)(g * H + j) * D + f]
                    : W_hh[(size_t)(g * H + j) * H + (f - D)];
            }
        g_WArz[(blk * KPA + kp) * 8 + c] =
            make_ulonglong2(packf2(v[0][0], v[0][1]), packf2(v[1][0], v[1][1]));
        ((ull*)&g_WAn[(blk * KPA + kp) * 4 + cg])[ci] = packf2(v[2][0], v[2][1]);
    } else if (bid < NPA + NPD) {
        int idx = (bid - NPA) * 256 + threadIdx.x;   // d*KPH + kp
        int d  = idx / KPH;
        int kp = idx - d * KPH;
        int blk = d >> 2, dof = d & 3;
        float m0 = W_dec[(size_t)d * H + 2 * kp];
        float m1 = W_dec[(size_t)d * H + 2 * kp + 1];
        float s0 = W_dec[(size_t)(D + d) * H + 2 * kp];
        float s1 = W_dec[(size_t)(D + d) * H + 2 * kp + 1];
        g_WD[(blk * KPH + kp) * 4 + dof] =
            make_ulonglong2(packf2(m0, m1), packf2(s0, s1));
    } else {
        int r = (bid - NPA - NPD) * 256 + threadIdx.x;
        if (r < H3) {
            const float* wi = W_ih + (size_t)r * H;
            double acc = (double)b_gru[r];
            for (int k = 0; k < H; k++)
                acc += (double)wi[k] * (double)b_enc[k];
            g_bcomb[r] = (float)acc;
        }
    }
}

// ---------------- init: x0 into act[0].x, zero act[0].h, snapshot barrier ---
__global__ void init_state(const float* __restrict__ x0)  // [B, D]
{
    int i = blockIdx.x * blockDim.x + threadIdx.x;
    if (i == 0) g_base = g_arrive;    // stable between launches
    if (i < B * D) {
        int b = i >> 9, d = i & (D - 1);
        ((float*)g_act[0])[(((d >> 1) * B) + b) * 2 + (d & 1)] = x0[i];
    }
    if (i < KPH * B) g_act[0][KPX * B + i] = 0ull;
}

// ---------------- grid-wide barrier (deterministic target) ------------------
__device__ __forceinline__ void grid_sync(unsigned target) {
    __syncthreads();
    if (threadIdx.x == 0) {
        asm volatile("red.release.gpu.global.add.u32 [%0], 1;"
                     :: "l"(&g_arrive) : "memory");
        unsigned v;
        do {
            asm volatile("ld.acquire.gpu.global.u32 %0, [%1];"
                         : "=r"(v) : "l"(&g_arrive) : "memory");
        } while ((int)(v - target) < 0);
    }
    __syncthreads();
}

// ---------------- persistent GRU kernel -------------------------------------
// 128 blocks x 512 threads, weights SMEM-resident, fused seg2 (decoder +
// next-step h-gate GEMM). r15: arrive/wait split in seg2 tail (out[] stores
// overlap the barrier wait), redundant sync removed, deeper unrolls.
__global__ void __launch_bounds__(NTHR, 1) gru_persistent(
    const float* __restrict__ b_n,
    const float* __restrict__ b_dec,
    const float* __restrict__ eps,
    float* __restrict__ out,
    int steps)
{
    extern __shared__ __align__(16) ull sm[];
    const ulonglong2* sArz = (const ulonglong2*)(sm + SM_ARZ);
    const ulonglong2* sAn  = (const ulonglong2*)(sm + SM_AN);
    const ulonglong2* sWD  = (const ulonglong2*)(sm + SM_WD);
    ull* red = sm + SM_RED;

    const int tid  = threadIdx.x;
    const int lane = tid & 31;
    const int w    = tid >> 5;
    const int blk  = blockIdx.x;

    const int cg = lane >> 3;       // col group (cols 2cg, 2cg+1)
    const int bq = lane & 7;        // batch quad (batches 4bq..4bq+3)

    const size_t plane = (size_t)steps * (B * D);

    // ---- preload the block's weight slice into smem (once) ----
    {
        const ulonglong2* srcA = g_WArz + (size_t)blk * KPA * 8;
        const ulonglong2* srcN = g_WAn  + (size_t)blk * KPA * 4;
        const ulonglong2* srcD = g_WD   + (size_t)blk * KPH * 4;
        ulonglong2* dA = (ulonglong2*)(sm + SM_ARZ);
        ulonglong2* dN = (ulonglong2*)(sm + SM_AN);
        ulonglong2* dD = (ulonglong2*)(sm + SM_WD);
        for (int i = tid; i < KPA * 8; i += NTHR) dA[i] = __ldg(srcA + i);
        for (int i = tid; i < KPA * 4; i += NTHR) dN[i] = __ldg(srcN + i);
        for (int i = tid; i < KPH * 4; i += NTHR) dD[i] = __ldg(srcD + i);
    }
    __syncthreads();

    // reducer/gating thread constants (tid < 256): target (cG, b)
    const int cG  = tid >> 5;
    const int bR  = tid & 31;
    const int slotbase = ((cG >> 1) * 8 + (bR >> 2));   // cgg*8 + bqq
    const int offR = (cG & 1) * 4 + (bR & 3);           // cii*4 + bii
    const int jG   = blk * 8 + cG;
    const int fiG  = ((KPX + (jG >> 1)) * B + bR) * 2 + (jG & 1);

    // phase-B output thread constants (tid < 128)
    const int dofO = tid >> 5;
    const int bO   = tid & 31;
    const int dO   = blk * 4 + dofO;

    // loop-invariant biases in registers
    float bc0 = 0.f, bc1 = 0.f, bc2 = 0.f, bnv = 0.f;
    if (tid < 256) {
        bc0 = g_bcomb[jG];
        bc1 = g_bcomb[H + jG];
        bc2 = g_bcomb[2 * H + jG];
        bnv = __ldg(b_n + jG);
    }
    float bd0 = 0.f, bd1 = 0.f;
    if (tid < 128) {
        bd0 = __ldg(b_dec + dO);
        bd1 = __ldg(b_dec + D + dO);
    }

    // h_prev register: this thread computed h[jG][bR] last step; h0 = 0
    float hprev = 0.f;

    // barrier bookkeeping: deterministic arrival targets
    unsigned tgt = g_base + NBLK;

    ull* mySlot = red + (size_t)(w * 32 + lane) * SST;

    // carried h-part gate partials for the CURRENT step (h_0 = 0 -> zeros)
    ull aR[2][4], aZ[2][4], aNh[2][4];
    #pragma unroll
    for (int ci = 0; ci < 2; ci++)
        #pragma unroll
        for (int bi = 0; bi < 4; bi++)
            { aR[ci][bi] = 0; aZ[ci][bi] = 0; aNh[ci][bi] = 0; }

    for (int t = 0; t < steps; t++) {
        const ull* actR = g_act[t & 1];
        ull*       actW = g_act[(t & 1) ^ 1];

        // prefetch eps for this step's sampling tail (no dependencies)
        float epsv = 0.f;
        size_t oO = (size_t)t * (B * D) + (size_t)bO * D + dO;
        if (tid < 128) epsv = __ldg(eps + oO);

        // ============ segment 1: x-part gate GEMM (into carried partials) ===
        ull aNx[2][4];
        #pragma unroll
        for (int ci = 0; ci < 2; ci++)
            #pragma unroll
            for (int bi = 0; bi < 4; bi++) aNx[ci][bi] = 0;

        {
            int kp0 = w * (KPX / NW);
            #pragma unroll
            for (int q = 0; q < KPX / NW; q++) {
                int kp = kp0 + q;
                ulonglong2 a01 = __ldcg((const ulonglong2*)(actR + kp * B + bq * 4));
                ulonglong2 a23 = __ldcg((const ulonglong2*)(actR + kp * B + bq * 4 + 2));
                ulonglong2 rz0 = sArz[kp * 8 + 2 * cg];
                ulonglong2 rz1 = sArz[kp * 8 + 2 * cg + 1];
                ulonglong2 nn  = sAn [kp * 4 + cg];
                ull av[4] = { a01.x, a01.y, a23.x, a23.y };
                #pragma unroll
                for (int bi = 0; bi < 4; bi++) {
                    fma2(aR[0][bi],  rz0.x, av[bi]);
                    fma2(aZ[0][bi],  rz0.y, av[bi]);
                    fma2(aNx[0][bi], nn.x,  av[bi]);
                    fma2(aR[1][bi],  rz1.x, av[bi]);
                    fma2(aZ[1][bi],  rz1.y, av[bi]);
                    fma2(aNx[1][bi], nn.y,  av[bi]);
                }
            }
        }

        // ---- pre-summed, quantity-paired reduction: 2 chunks ----
        // TRAILSYNC: chunk1 needs a trailing sync (chunk2 reuses slots);
        // chunk2's reads are protected by the following grid_sync.
        ull sRZ = 0, sNN = 0;
#define RED_CHUNK2(ACC0, ACC1, SDST, TRAILSYNC)                               \
        {                                                                     \
            _Pragma("unroll")                                                 \
            for (int ci = 0; ci < 2; ci++)                                    \
                _Pragma("unroll")                                             \
                for (int bi = 0; bi < 4; bi++) {                              \
                    float2 u0 = upk(ACC0[ci][bi]);                            \
                    float2 u1 = upk(ACC1[ci][bi]);                            \
                    mySlot[ci * 4 + bi] = packf2(u0.x + u0.y, u1.x + u1.y);   \
                }                                                             \
            __syncthreads();                                                  \
            if (tid < 256) {                                                  \
                ull tv[8];                                                    \
                _Pragma("unroll")                                             \
                for (int ww = 0; ww < 8; ww++)                                \
                    tv[ww] = red[(size_t)(ww * 32 + slotbase) * SST + offR];  \
                _Pragma("unroll")                                             \
                for (int ww = 8; ww < 16; ww++)                               \
                    tv[ww - 8] = add2o(tv[ww - 8],                            \
                        red[(size_t)(ww * 32 + slotbase) * SST + offR]);      \
                _Pragma("unroll")                                             \
                for (int sW = 4; sW > 0; sW >>= 1)                            \
                    _Pragma("unroll")                                         \
                    for (int i = 0; i < sW; i++)                              \
                        tv[i] = add2o(tv[i], tv[i + sW]);                     \
                SDST = tv[0];                                                 \
            }                                                                 \
            if (TRAILSYNC) __syncthreads();                                   \
        }
        RED_CHUNK2(aR,  aZ,  sRZ, 1)
        RED_CHUNK2(aNx, aNh, sNN, 0)
#undef RED_CHUNK2

        if (tid < 256) {   // gating: thread (cG, bR) -> h_new[jG][bR]
            float2 urz = upk(sRZ);
            float2 unn = upk(sNN);
            float pr  = urz.x + bc0;
            float pz  = urz.y + bc1;
            float inx = unn.x + bc2;
            float hnv = unn.y;
            float r = sigmoid_acc(pr);
            float z = sigmoid_acc(pz);
            float n = tanh_acc(fmaf(r, hnv + bnv, inx));
            float hnew = n + z * (hprev - n);
            hprev = hnew;
            ((float*)actW)[fiG] = hnew;
        }
        grid_sync(tgt);  tgt += NBLK;

        // ============ segment 2: fused decoder + next-step h-gate GEMM ======
        ull AM[4], AS[4];
        #pragma unroll
        for (int bi = 0; bi < 4; bi++) { AM[bi] = 0; AS[bi] = 0; }
        #pragma unroll
        for (int ci = 0; ci < 2; ci++)
            #pragma unroll
            for (int bi = 0; bi < 4; bi++)
                { aR[ci][bi] = 0; aZ[ci][bi] = 0; aNh[ci][bi] = 0; }
        {
            int kp0 = w * (KPH / NW);
            #pragma unroll 4
            for (int q = 0; q < KPH / NW; q++) {
                int kp  = kp0 + q;           // decoder weight index
                int kpa = KPX + kp;          // gate weight / activation index
                ulonglong2 a01 = __ldcg((const ulonglong2*)(actW + kpa * B + bq * 4));
                ulonglong2 a23 = __ldcg((const ulonglong2*)(actW + kpa * B + bq * 4 + 2));
                ulonglong2 rz0 = sArz[kpa * 8 + 2 * cg];
                ulonglong2 rz1 = sArz[kpa * 8 + 2 * cg + 1];
                ulonglong2 nn  = sAn [kpa * 4 + cg];
                ulonglong2 wv  = sWD [kp * 4 + cg];
                ull av[4] = { a01.x, a01.y, a23.x, a23.y };
                #pragma unroll
                for (int bi = 0; bi < 4; bi++) {
                    fma2(AM[bi], wv.x, av[bi]);
                    fma2(AS[bi], wv.y, av[bi]);
                    fma2(aR[0][bi],  rz0.x, av[bi]);
                    fma2(aZ[0][bi],  rz0.y, av[bi]);
                    fma2(aNh[0][bi], nn.x,  av[bi]);
                    fma2(aR[1][bi],  rz1.x, av[bi]);
                    fma2(aZ[1][bi],  rz1.y, av[bi]);
                    fma2(aNh[1][bi], nn.y,  av[bi]);
                }
            }
        }
        {   // pre-summed (mu,ls) partials: 4 ulls per thread
            #pragma unroll
            for (int bi = 0; bi < 4; bi++) {
                float2 um = upk(AM[bi]);
                float2 us = upk(AS[bi]);
                mySlot[bi] = packf2(um.x + um.y, us.x + us.y);
            }
            __syncthreads();
        }
        // tail: compute outputs; write x BEFORE arrival, out[] AFTER arrival
        float xn = 0.f, muv = 0.f, sigv = 0.f;
        if (tid < 128) {
            int bqq = bO >> 2, bii = bO & 3;
            ull tv[8];
            #pragma unroll
            for (int ww = 0; ww < 8; ww++)
                tv[ww] = red[(size_t)(ww * 32 + dofO * 8 + bqq) * SST + bii];
            #pragma unroll
            for (int ww = 8; ww < 16; ww++)
                tv[ww - 8] = add2o(tv[ww - 8],
                    red[(size_t)(ww * 32 + dofO * 8 + bqq) * SST + bii]);
            #pragma unroll
            for (int sW = 4; sW > 0; sW >>= 1)
                #pragma unroll
                for (int i = 0; i < sW; i++)
                    tv[i] = add2o(tv[i], tv[i + sW]);
            float2 ums = upk(tv[0]);
            muv  = ums.x + bd0;
            float ls = ums.y + bd1;
            sigv = exp_acc(ls);
            xn   = fmaf(sigv, epsv, muv);
            ((float*)actW)[(((dO >> 1) * B) + bO) * 2 + (dO & 1)] = xn;
        }
        // arrive (release covers the x writes via the preceding syncthreads)
        __syncthreads();
        if (tid == 0)
            asm volatile("red.release.gpu.global.add.u32 [%0], 1;"
                         :: "l"(&g_arrive) : "memory");
        // out[] stores overlap the barrier wait (read only after kernel end)
        if (tid < 128) {
            out[oO]             = xn;
            out[plane + oO]     = muv;
            out[2 * plane + oO] = sigv;
        }
        if (tid == 0) {
            unsigned v;
            do {
                asm volatile("ld.acquire.gpu.global.u32 %0, [%1];"
                             : "=r"(v) : "l"(&g_arrive) : "memory");
            } while ((int)(v - tgt) < 0);
        }
        __syncthreads();
        tgt += NBLK;
    }
}

// ---------------- launch ----------------------------------------------------
extern "C" void kernel_launch(void* const* d_in, const int* in_sizes, int n_in,
                              void* d_out, int out_size)
{
    const float* x0    = (const float*)d_in[0];
    const float* eps   = (const float*)d_in[1];
    const float* W_enc = (const float*)d_in[2];
    const float* b_enc = (const float*)d_in[3];
    const float* W_ih  = (const float*)d_in[4];
    const float* W_hh  = (const float*)d_in[5];
    const float* b_gru = (const float*)d_in[6];
    const float* b_n   = (const float*)d_in[7];
    const float* W_dec = (const float*)d_in[8];
    const float* b_dec = (const float*)d_in[9];

    int steps = in_sizes[1] / (B * D);
    float* out = (float*)d_out;

    const int smem_bytes = SM_TOT * sizeof(ull);   // 217088
    cudaFuncSetAttribute(gru_persistent,
                         cudaFuncAttributeMaxDynamicSharedMemorySize, smem_bytes);

    precompute_wcomb<<<H3 / 8, 256>>>(W_ih, W_enc);
    fused_pack<<<NPA + NPD + NPB, 256>>>(W_hh, W_dec, W_ih, b_enc, b_gru);
    init_state<<<(KPH * B + 255) / 256, 256>>>(x0);
    gru_persistent<<<NBLK, NTHR, smem_bytes>>>(b_n, b_dec, eps, out, steps);
}

// round 16
// speedup vs baseline: 1.0813x; 1.0813x over previous
#include <cuda_runtime.h>
#include <math.h>

#define B 32
#define D 512
#define H 1024
#define H3 (3*H)
#define NBLK 128
#define NTHR 512
#define NW   16            // warps per block
#define KPX 256            // x feature-pairs
#define KPH 512            // h feature-pairs
#define KPA (KPX+KPH)      // 768 combined feature-pairs (phase A)
#define SST 9              // padded smem slot stride (ull), 8 payload + 1 pad

// smem layout (ull units) — r12/r14 proven layout
#define SM_ARZ 0                       // 12288 ull  (6144 ulonglong2)
#define SM_AN  12288                   //  6144 ull  (3072 ulonglong2)
#define SM_WD  18432                   //  4096 ull  (2048 ulonglong2)
#define SM_RED 22528                   //  4608 ull  (512 slots * 9)
#define SM_TOT 27136                   // 217088 bytes

typedef unsigned long long ull;

// ---------------- persistent device scratch --------------------------------
__device__ __align__(16) float g_Wcomb[H3 * D];            // temp: W_ih @ W_enc
__device__ float g_bcomb[H3];
__device__ __align__(16) ulonglong2 g_WArz[NBLK * KPA * 8];
__device__ __align__(16) ulonglong2 g_WAn [NBLK * KPA * 4];
__device__ __align__(16) ulonglong2 g_WD  [NBLK * KPH * 4];
__device__ __align__(16) ull g_act[2][KPA * B + 64];
__device__ unsigned g_arrive;
__device__ unsigned g_base;     // snapshot of g_arrive at launch start

// ---------------- packed f32x2 helpers --------------------------------------
__device__ __forceinline__ void fma2(ull& acc, ull a, ull b) {
    asm("fma.rn.f32x2 %0, %1, %2, %0;" : "+l"(acc) : "l"(a), "l"(b));
}
__device__ __forceinline__ ull add2o(ull a, ull b) {
    ull c;
    asm("add.rn.f32x2 %0, %1, %2;" : "=l"(c) : "l"(a), "l"(b));
    return c;
}
__device__ __forceinline__ float2 upk(ull u) {
    float a, b;
    asm("mov.b64 {%0, %1}, %2;" : "=f"(a), "=f"(b) : "l"(u));
    return make_float2(a, b);
}
__device__ __forceinline__ ull packf2(float lo, float hi) {
    ull u; asm("mov.b64 %0, {%1, %2};" : "=l"(u) : "f"(lo), "f"(hi)); return u;
}

// ---------------- fast-math-immune precise fp32 transcendentals ------------
__device__ __forceinline__ float exp_acc(float x) {
    x = fminf(fmaxf(x, -80.f), 80.f);
    float t = fmaf(x, 1.4426950408889634f, 12582912.f);
    float k = t - 12582912.f;
    float r = fmaf(k, -0.693359375f, x);
    r = fmaf(k, 2.12194440054690583e-4f, r);
    float p = 1.9841269841e-4f;
    p = fmaf(p, r, 1.3888888889e-3f);
    p = fmaf(p, r, 8.3333333333e-3f);
    p = fmaf(p, r, 4.1666666667e-2f);
    p = fmaf(p, r, 1.6666666667e-1f);
    p = fmaf(p, r, 0.5f);
    float y = fmaf(p, r * r, r) + 1.0f;
    int ki = (int)k;
    float s = __int_as_float((ki + 127) << 23);
    return y * s;
}
__device__ __forceinline__ float sigmoid_acc(float x) {
    return __frcp_rn(1.0f + exp_acc(-x));
}
__device__ __forceinline__ float tanh_acc(float x) {
    float ax = fabsf(x);
    float e = exp_acc(2.0f * ax);
    float t = fmaf(-2.0f, __frcp_rn(e + 1.0f), 1.0f);
    return (x < 0.f) ? -t : t;
}

// ---------------- precompute: W_comb = W_ih @ W_enc (Kahan) -----------------
__global__ void __launch_bounds__(256) precompute_wcomb(
    const float* __restrict__ W_ih, const float* __restrict__ W_enc)
{
    __shared__ float wih[8][H];
    int r0 = blockIdx.x * 8;
    for (int i = threadIdx.x; i < 8 * H; i += 256)
        wih[i >> 10][i & (H - 1)] = W_ih[(size_t)r0 * H + i];
    __syncthreads();
    int d0 = threadIdx.x, d1 = threadIdx.x + 256;
    float s[16], c[16];
    #pragma unroll
    for (int j = 0; j < 16; j++) { s[j] = 0.f; c[j] = 0.f; }
    for (int k = 0; k < H; k++) {
        float e0 = __ldg(&W_enc[(size_t)k * D + d0]);
        float e1 = __ldg(&W_enc[(size_t)k * D + d1]);
        #pragma unroll
        for (int j = 0; j < 8; j++) {
            float w = wih[j][k];
            float tp = __fmul_rn(w, e0);
            float y  = __fsub_rn(tp, c[2*j]);
            float s2 = __fadd_rn(s[2*j], y);
            c[2*j]   = __fsub_rn(__fsub_rn(s2, s[2*j]), y);
            s[2*j]   = s2;
            tp = __fmul_rn(w, e1);
            y  = __fsub_rn(tp, c[2*j+1]);
            s2 = __fadd_rn(s[2*j+1], y);
            c[2*j+1] = __fsub_rn(__fsub_rn(s2, s[2*j+1]), y);
            s[2*j+1] = s2;
        }
    }
    #pragma unroll
    for (int j = 0; j < 8; j++) {
        g_Wcomb[(size_t)(r0 + j) * D + d0] = s[2*j];
        g_Wcomb[(size_t)(r0 + j) * D + d1] = s[2*j+1];
    }
}

// ---------------- fused pack: pack_A + pack_D + bcomb ----------------------
#define NPA ((H * KPA) / 256)
#define NPD ((D * KPH) / 256)
#define NPB ((H3 + 255) / 256)

__global__ void __launch_bounds__(256) fused_pack(
    const float* __restrict__ W_hh,
    const float* __restrict__ W_dec,
    const float* __restrict__ W_ih,
    const float* __restrict__ b_enc,
    const float* __restrict__ b_gru)
{
    int bid = blockIdx.x;
    if (bid < NPA) {
        int idx = bid * 256 + threadIdx.x;   // j*KPA + kp
        int j  = idx / KPA;
        int kp = idx - j * KPA;
        int blk = j >> 3, c = j & 7, cg = c >> 1, ci = c & 1;
        float v[3][2];
        #pragma unroll
        for (int g = 0; g < 3; g++)
            #pragma unroll
            for (int e = 0; e < 2; e++) {
                int f = 2 * kp + e;
                v[g][e] = (f < D)
                    ? g_Wcomb[(size_t)(g * H + j) * D + f]
                    : W_hh[(size_t)(g * H + j) * H + (f - D)];
            }
        g_WArz[(blk * KPA + kp) * 8 + c] =
            make_ulonglong2(packf2(v[0][0], v[0][1]), packf2(v[1][0], v[1][1]));
        ((ull*)&g_WAn[(blk * KPA + kp) * 4 + cg])[ci] = packf2(v[2][0], v[2][1]);
    } else if (bid < NPA + NPD) {
        int idx = (bid - NPA) * 256 + threadIdx.x;   // d*KPH + kp
        int d  = idx / KPH;
        int kp = idx - d * KPH;
        int blk = d >> 2, dof = d & 3;
        float m0 = W_dec[(size_t)d * H + 2 * kp];
        float m1 = W_dec[(size_t)d * H + 2 * kp + 1];
        float s0 = W_dec[(size_t)(D + d) * H + 2 * kp];
        float s1 = W_dec[(size_t)(D + d) * H + 2 * kp + 1];
        g_WD[(blk * KPH + kp) * 4 + dof] =
            make_ulonglong2(packf2(m0, m1), packf2(s0, s1));
    } else {
        int r = (bid - NPA - NPD) * 256 + threadIdx.x;
        if (r < H3) {
            const float* wi = W_ih + (size_t)r * H;
            double acc = (double)b_gru[r];
            for (int k = 0; k < H; k++)
                acc += (double)wi[k] * (double)b_enc[k];
            g_bcomb[r] = (float)acc;
        }
    }
}

// ---------------- init: x0 into act[0].x, zero act[0].h, snapshot barrier ---
__global__ void init_state(const float* __restrict__ x0)  // [B, D]
{
    int i = blockIdx.x * blockDim.x + threadIdx.x;
    if (i == 0) g_base = g_arrive;    // stable between launches
    if (i < B * D) {
        int b = i >> 9, d = i & (D - 1);
        ((float*)g_act[0])[(((d >> 1) * B) + b) * 2 + (d & 1)] = x0[i];
    }
    if (i < KPH * B) g_act[0][KPX * B + i] = 0ull;
}

// ---------------- grid-wide barrier (deterministic target) ------------------
__device__ __forceinline__ void grid_sync(unsigned target) {
    __syncthreads();
    if (threadIdx.x == 0) {
        asm volatile("red.release.gpu.global.add.u32 [%0], 1;"
                     :: "l"(&g_arrive) : "memory");
        unsigned v;
        do {
            asm volatile("ld.acquire.gpu.global.u32 %0, [%1];"
                         : "=r"(v) : "l"(&g_arrive) : "memory");
        } while ((int)(v - target) < 0);
    }
    __syncthreads();
}

// ---------------- persistent GRU kernel -------------------------------------
// 128 blocks x 512 threads, weights SMEM-resident, fused seg2 (decoder +
// next-step h-gate GEMM) — r14 structure & pragmas. r16 delta vs r14: only
// (a) arrive/wait split in the seg2 tail so out[] stores overlap the barrier
// wait, and (b) redundant trailing sync after reduction chunk 2 removed.
__global__ void __launch_bounds__(NTHR, 1) gru_persistent(
    const float* __restrict__ b_n,
    const float* __restrict__ b_dec,
    const float* __restrict__ eps,
    float* __restrict__ out,
    int steps)
{
    extern __shared__ __align__(16) ull sm[];
    const ulonglong2* sArz = (const ulonglong2*)(sm + SM_ARZ);
    const ulonglong2* sAn  = (const ulonglong2*)(sm + SM_AN);
    const ulonglong2* sWD  = (const ulonglong2*)(sm + SM_WD);
    ull* red = sm + SM_RED;

    const int tid  = threadIdx.x;
    const int lane = tid & 31;
    const int w    = tid >> 5;
    const int blk  = blockIdx.x;

    const int cg = lane >> 3;       // col group (cols 2cg, 2cg+1)
    const int bq = lane & 7;        // batch quad (batches 4bq..4bq+3)

    const size_t plane = (size_t)steps * (B * D);

    // ---- preload the block's weight slice into smem (once) ----
    {
        const ulonglong2* srcA = g_WArz + (size_t)blk * KPA * 8;
        const ulonglong2* srcN = g_WAn  + (size_t)blk * KPA * 4;
        const ulonglong2* srcD = g_WD   + (size_t)blk * KPH * 4;
        ulonglong2* dA = (ulonglong2*)(sm + SM_ARZ);
        ulonglong2* dN = (ulonglong2*)(sm + SM_AN);
        ulonglong2* dD = (ulonglong2*)(sm + SM_WD);
        for (int i = tid; i < KPA * 8; i += NTHR) dA[i] = __ldg(srcA + i);
        for (int i = tid; i < KPA * 4; i += NTHR) dN[i] = __ldg(srcN + i);
        for (int i = tid; i < KPH * 4; i += NTHR) dD[i] = __ldg(srcD + i);
    }
    __syncthreads();

    // reducer/gating thread constants (tid < 256): target (cG, b)
    const int cG  = tid >> 5;
    const int bR  = tid & 31;
    const int slotbase = ((cG >> 1) * 8 + (bR >> 2));   // cgg*8 + bqq
    const int offR = (cG & 1) * 4 + (bR & 3);           // cii*4 + bii
    const int jG   = blk * 8 + cG;
    const int fiG  = ((KPX + (jG >> 1)) * B + bR) * 2 + (jG & 1);

    // phase-B output thread constants (tid < 128)
    const int dofO = tid >> 5;
    const int bO   = tid & 31;
    const int dO   = blk * 4 + dofO;

    // loop-invariant biases in registers
    float bc0 = 0.f, bc1 = 0.f, bc2 = 0.f, bnv = 0.f;
    if (tid < 256) {
        bc0 = g_bcomb[jG];
        bc1 = g_bcomb[H + jG];
        bc2 = g_bcomb[2 * H + jG];
        bnv = __ldg(b_n + jG);
    }
    float bd0 = 0.f, bd1 = 0.f;
    if (tid < 128) {
        bd0 = __ldg(b_dec + dO);
        bd1 = __ldg(b_dec + D + dO);
    }

    // h_prev register: this thread computed h[jG][bR] last step; h0 = 0
    float hprev = 0.f;

    // barrier bookkeeping: deterministic arrival targets
    unsigned tgt = g_base + NBLK;

    ull* mySlot = red + (size_t)(w * 32 + lane) * SST;

    // carried h-part gate partials for the CURRENT step (h_0 = 0 -> zeros)
    ull aR[2][4], aZ[2][4], aNh[2][4];
    #pragma unroll
    for (int ci = 0; ci < 2; ci++)
        #pragma unroll
        for (int bi = 0; bi < 4; bi++)
            { aR[ci][bi] = 0; aZ[ci][bi] = 0; aNh[ci][bi] = 0; }

    for (int t = 0; t < steps; t++) {
        const ull* actR = g_act[t & 1];
        ull*       actW = g_act[(t & 1) ^ 1];

        // prefetch eps for this step's sampling tail (no dependencies)
        float epsv = 0.f;
        size_t oO = (size_t)t * (B * D) + (size_t)bO * D + dO;
        if (tid < 128) epsv = __ldg(eps + oO);

        // ============ segment 1: x-part gate GEMM (into carried partials) ===
        ull aNx[2][4];
        #pragma unroll
        for (int ci = 0; ci < 2; ci++)
            #pragma unroll
            for (int bi = 0; bi < 4; bi++) aNx[ci][bi] = 0;

        {
            int kp0 = w * (KPX / NW);
            #pragma unroll 4
            for (int q = 0; q < KPX / NW; q++) {
                int kp = kp0 + q;
                ulonglong2 a01 = __ldcg((const ulonglong2*)(actR + kp * B + bq * 4));
                ulonglong2 a23 = __ldcg((const ulonglong2*)(actR + kp * B + bq * 4 + 2));
                ulonglong2 rz0 = sArz[kp * 8 + 2 * cg];
                ulonglong2 rz1 = sArz[kp * 8 + 2 * cg + 1];
                ulonglong2 nn  = sAn [kp * 4 + cg];
                ull av[4] = { a01.x, a01.y, a23.x, a23.y };
                #pragma unroll
                for (int bi = 0; bi < 4; bi++) {
                    fma2(aR[0][bi],  rz0.x, av[bi]);
                    fma2(aZ[0][bi],  rz0.y, av[bi]);
                    fma2(aNx[0][bi], nn.x,  av[bi]);
                    fma2(aR[1][bi],  rz1.x, av[bi]);
                    fma2(aZ[1][bi],  rz1.y, av[bi]);
                    fma2(aNx[1][bi], nn.y,  av[bi]);
                }
            }
        }

        // ---- pre-summed, quantity-paired reduction: 2 chunks ----
        // chunk1 keeps its trailing sync (chunk2 reuses slots); chunk2's
        // reads are protected by the following grid_sync's __syncthreads.
        ull sRZ = 0, sNN = 0;
#define RED_CHUNK2(ACC0, ACC1, SDST, TRAILSYNC)                               \
        {                                                                     \
            _Pragma("unroll")                                                 \
            for (int ci = 0; ci < 2; ci++)                                    \
                _Pragma("unroll")                                             \
                for (int bi = 0; bi < 4; bi++) {                              \
                    float2 u0 = upk(ACC0[ci][bi]);                            \
                    float2 u1 = upk(ACC1[ci][bi]);                            \
                    mySlot[ci * 4 + bi] = packf2(u0.x + u0.y, u1.x + u1.y);   \
                }                                                             \
            __syncthreads();                                                  \
            if (tid < 256) {                                                  \
                ull tv[8];                                                    \
                _Pragma("unroll")                                             \
                for (int ww = 0; ww < 8; ww++)                                \
                    tv[ww] = red[(size_t)(ww * 32 + slotbase) * SST + offR];  \
                _Pragma("unroll")                                             \
                for (int ww = 8; ww < 16; ww++)                               \
                    tv[ww - 8] = add2o(tv[ww - 8],                            \
                        red[(size_t)(ww * 32 + slotbase) * SST + offR]);      \
                _Pragma("unroll")                                             \
                for (int sW = 4; sW > 0; sW >>= 1)                            \
                    _Pragma("unroll")                                         \
                    for (int i = 0; i < sW; i++)                              \
                        tv[i] = add2o(tv[i], tv[i + sW]);                     \
                SDST = tv[0];                                                 \
            }                                                                 \
            if (TRAILSYNC) __syncthreads();                                   \
        }
        RED_CHUNK2(aR,  aZ,  sRZ, 1)
        RED_CHUNK2(aNx, aNh, sNN, 0)
#undef RED_CHUNK2

        if (tid < 256) {   // gating: thread (cG, bR) -> h_new[jG][bR]
            float2 urz = upk(sRZ);
            float2 unn = upk(sNN);
            float pr  = urz.x + bc0;
            float pz  = urz.y + bc1;
            float inx = unn.x + bc2;
            float hnv = unn.y;
            float r = sigmoid_acc(pr);
            float z = sigmoid_acc(pz);
            float n = tanh_acc(fmaf(r, hnv + bnv, inx));
            float hnew = n + z * (hprev - n);
            hprev = hnew;
            ((float*)actW)[fiG] = hnew;
        }
        grid_sync(tgt);  tgt += NBLK;

        // ============ segment 2: fused decoder + next-step h-gate GEMM ======
        ull AM[4], AS[4];
        #pragma unroll
        for (int bi = 0; bi < 4; bi++) { AM[bi] = 0; AS[bi] = 0; }
        #pragma unroll
        for (int ci = 0; ci < 2; ci++)
            #pragma unroll
            for (int bi = 0; bi < 4; bi++)
                { aR[ci][bi] = 0; aZ[ci][bi] = 0; aNh[ci][bi] = 0; }
        {
            int kp0 = w * (KPH / NW);
            #pragma unroll 2
            for (int q = 0; q < KPH / NW; q++) {
                int kp  = kp0 + q;           // decoder weight index
                int kpa = KPX + kp;          // gate weight / activation index
                ulonglong2 a01 = __ldcg((const ulonglong2*)(actW + kpa * B + bq * 4));
                ulonglong2 a23 = __ldcg((const ulonglong2*)(actW + kpa * B + bq * 4 + 2));
                ulonglong2 rz0 = sArz[kpa * 8 + 2 * cg];
                ulonglong2 rz1 = sArz[kpa * 8 + 2 * cg + 1];
                ulonglong2 nn  = sAn [kpa * 4 + cg];
                ulonglong2 wv  = sWD [kp * 4 + cg];
                ull av[4] = { a01.x, a01.y, a23.x, a23.y };
                #pragma unroll
                for (int bi = 0; bi < 4; bi++) {
                    fma2(AM[bi], wv.x, av[bi]);
                    fma2(AS[bi], wv.y, av[bi]);
                    fma2(aR[0][bi],  rz0.x, av[bi]);
                    fma2(aZ[0][bi],  rz0.y, av[bi]);
                    fma2(aNh[0][bi], nn.x,  av[bi]);
                    fma2(aR[1][bi],  rz1.x, av[bi]);
                    fma2(aZ[1][bi],  rz1.y, av[bi]);
                    fma2(aNh[1][bi], nn.y,  av[bi]);
                }
            }
        }
        {   // pre-summed (mu,ls) partials: 4 ulls per thread
            #pragma unroll
            for (int bi = 0; bi < 4; bi++) {
                float2 um = upk(AM[bi]);
                float2 us = upk(AS[bi]);
                mySlot[bi] = packf2(um.x + um.y, us.x + us.y);
            }
            __syncthreads();
        }
        // tail: compute outputs; write x BEFORE arrival, out[] AFTER arrival
        float xn = 0.f, muv = 0.f, sigv = 0.f;
        if (tid < 128) {
            int bqq = bO >> 2, bii = bO & 3;
            ull tv[8];
            #pragma unroll
            for (int ww = 0; ww < 8; ww++)
                tv[ww] = red[(size_t)(ww * 32 + dofO * 8 + bqq) * SST + bii];
            #pragma unroll
            for (int ww = 8; ww < 16; ww++)
                tv[ww - 8] = add2o(tv[ww - 8],
                    red[(size_t)(ww * 32 + dofO * 8 + bqq) * SST + bii]);
            #pragma unroll
            for (int sW = 4; sW > 0; sW >>= 1)
                #pragma unroll
                for (int i = 0; i < sW; i++)
                    tv[i] = add2o(tv[i], tv[i + sW]);
            float2 ums = upk(tv[0]);
            muv  = ums.x + bd0;
            float ls = ums.y + bd1;
            sigv = exp_acc(ls);
            xn   = fmaf(sigv, epsv, muv);
            ((float*)actW)[(((dO >> 1) * B) + bO) * 2 + (dO & 1)] = xn;
        }
        // arrive (release covers the x writes via the preceding syncthreads)
        __syncthreads();
        if (tid == 0)
            asm volatile("red.release.gpu.global.add.u32 [%0], 1;"
                         :: "l"(&g_arrive) : "memory");
        // out[] stores overlap the barrier wait (read only after kernel end)
        if (tid < 128) {
            out[oO]             = xn;
            out[plane + oO]     = muv;
            out[2 * plane + oO] = sigv;
        }
        if (tid == 0) {
            unsigned v;
            do {
                asm volatile("ld.acquire.gpu.global.u32 %0, [%1];"
                             : "=r"(v) : "l"(&g_arrive) : "memory");
            } while ((int)(v - tgt) < 0);
        }
        __syncthreads();
        tgt += NBLK;
    }
}

// ---------------- launch ----------------------------------------------------
extern "C" void kernel_launch(void* const* d_in, const int* in_sizes, int n_in,
                              void* d_out, int out_size)
{
    const float* x0    = (const float*)d_in[0];
    const float* eps   = (const float*)d_in[1];
    const float* W_enc = (const float*)d_in[2];
    const float* b_enc = (const float*)d_in[3];
    const float* W_ih  = (const float*)d_in[4];
    const float* W_hh  = (const float*)d_in[5];
    const float* b_gru = (const float*)d_in[6];
    const float* b_n   = (const float*)d_in[7];
    const float* W_dec = (const float*)d_in[8];
    const float* b_dec = (const float*)d_in[9];

    int steps = in_sizes[1] / (B * D);
    float* out = (float*)d_out;

    const int smem_bytes = SM_TOT * sizeof(ull);   // 217088
    cudaFuncSetAttribute(gru_persistent,
                         cudaFuncAttributeMaxDynamicSharedMemorySize, smem_bytes);

    precompute_wcomb<<<H3 / 8, 256>>>(W_ih, W_enc);
    fused_pack<<<NPA + NPD + NPB, 256>>>(W_hh, W_dec, W_ih, b_enc, b_gru);
    init_state<<<(KPH * B + 255) / 256, 256>>>(x0);
    gru_persistent<<<NBLK, NTHR, smem_bytes>>>(b_n, b_dec, eps, out, steps);
}